// round 10
// baseline (speedup 1.0000x reference)
#include <cuda_runtime.h>
#include <cstdint>

// Conv4D via mma.sync tf32 (portable sm_80+ PTX).
// x(8,16,32,24,24,24) NCLDHW * W(32,16,3,3,3,3) OILDHW -> out(8,32,30,22,22,22), +3*b.
//
// R8: 512 threads (16 warps, 4/SMSP) for LDS/tensor overlap; k-quad layout ->
// every fragment load is one ld.shared.v4.u32 serving BOTH k-steps; round-robin
// tile map (33 m-tiles: warp0 x3, rest x2); double-buffered x/W via cp.async.

#define XBUF 37120                 // 580 rows * 64B
#define OFF_X0 0
#define OFF_X1 37120
#define OFF_W0 74240               // 288 rows * 64B = 18432
#define OFF_W1 92672
#define OFF_BS 111104
#define SMEM_TOTAL 111232

#define L_STRIDE 13824             // 24*24*24
#define OUT_CO_STRIDE 319440       // 30*22*22*22

__device__ uint32_t g_xp[56623104];    // [n][l][d][m=576][16 ci quad-interleaved]
__device__ uint32_t g_wp[41472];       // [s][tap][co][16 ci quad-interleaved]

static __device__ __forceinline__ uint32_t s2u(const void* p) {
    uint32_t a;
    asm("{ .reg .u64 t; cvta.to.shared.u64 t, %1; cvt.u32.u64 %0, t; }" : "=r"(a) : "l"(p));
    return a;
}
static __device__ __forceinline__ uint32_t tf32rn(float f) {
    uint32_t o;
    asm("cvt.rna.tf32.f32 %0, %1;" : "=r"(o) : "f"(f));
    return o;
}
static __device__ __forceinline__ void cp16(uint32_t dst, const void* src) {
    asm volatile("cp.async.cg.shared.global [%0], [%1], 16;" :: "r"(dst), "l"(src) : "memory");
}
static __device__ __forceinline__ void lds4(uint32_t& r0, uint32_t& r1, uint32_t& r2, uint32_t& r3, uint32_t a) {
    asm volatile("ld.shared.v4.u32 {%0,%1,%2,%3}, [%4];" : "=r"(r0), "=r"(r1), "=r"(r2), "=r"(r3) : "r"(a));
}

#define MMA_TF32(d, a0, a1, a2, a3, b0, b1) \
    asm volatile("mma.sync.aligned.m16n8k8.row.col.f32.tf32.tf32.f32 " \
        "{%0,%1,%2,%3}, {%4,%5,%6,%7}, {%8,%9}, {%0,%1,%2,%3};" \
        : "+f"((d)[0]), "+f"((d)[1]), "+f"((d)[2]), "+f"((d)[3]) \
        : "r"(a0), "r"(a1), "r"(a2), "r"(a3), "r"(b0), "r"(b1))

// ---- prepass: x -> tf32 bits; within-row order pos = (ci%4)*4 + ci/4 ----
__global__ __launch_bounds__(256)
void prep_x_kernel(const float* __restrict__ x) {
    const int d = blockIdx.x, l = blockIdx.y, n = blockIdx.z;
    const int tid = threadIdx.x;
    const size_t src0 = ((size_t)(n * 16) * 32 + l) * L_STRIDE + d * 576;
    uint32_t* dst0 = g_xp + (((size_t)(n * 32 + l) * 24 + d) * 576) * 16;
    for (int m = tid; m < 576; m += 256) {
        uint32_t v[16];
        #pragma unroll
        for (int ci = 0; ci < 16; ci++)
            v[(ci & 3) * 4 + (ci >> 2)] = tf32rn(x[src0 + (size_t)ci * (32 * L_STRIDE) + m]);
        uint32_t* dr = dst0 + m * 16;
        #pragma unroll
        for (int q = 0; q < 4; q++)
            *(uint4*)(dr + q * 4) = make_uint4(v[q*4], v[q*4+1], v[q*4+2], v[q*4+3]);
    }
}

// ---- prepass: W -> tf32 bits, [s][tap][co][pos], ci = (pos>>2) + (pos&3)*4 ----
__global__ __launch_bounds__(256)
void prep_w_kernel(const float* __restrict__ W) {
    int e = blockIdx.x * 256 + threadIdx.x;     // 0..41471
    int pos = e & 15;
    int co  = (e >> 4) & 31;
    int t9  = e >> 9;                            // s*9+tap
    int s   = t9 / 9, tap = t9 - 9 * s;
    int lk = s / 3,  dk = s - 3 * lk;
    int hk = tap / 3, wk = tap - 3 * hk;
    int ci = (pos >> 2) + (pos & 3) * 4;
    g_wp[e] = tf32rn(W[(size_t)(co * 16 + ci) * 81 + lk * 27 + dk * 9 + hk * 3 + wk]);
}

extern __shared__ char smem[];

__global__ __launch_bounds__(512)
void conv4d_mma_kernel(const float* __restrict__ b, float* __restrict__ out)
{
    const int d_out = blockIdx.x;   // 0..21
    const int l_out = blockIdx.y;   // 0..29
    const int n     = blockIdx.z;   // 0..7
    const int tid   = threadIdx.x;
    const int wid   = tid >> 5;     // 0..15
    const int lid   = tid & 31;
    const int c     = lid & 3;
    const int g     = lid >> 2;
    const uint32_t sb = s2u(smem);

    if (tid < 32) ((float*)(smem + OFF_BS))[tid] = 3.0f * b[tid];

    auto stage = [&](int s) {
        const int lk = s / 3, dk = s - 3 * lk;
        const uint32_t xo = sb + ((s & 1) ? OFF_X1 : OFF_X0);
        const uint32_t wo = sb + ((s & 1) ? OFF_W1 : OFF_W0);
        const uint32_t* xs = g_xp + (((size_t)(n * 32 + (l_out + lk)) * 24 + (d_out + dk)) * 576) * 16;
        #pragma unroll
        for (int j5 = 0; j5 < 5; j5++) {
            int j = tid + j5 * 512;              // 0..2303 (need 2304)
            if (j5 < 4 || j < 2304)
                cp16(xo + (uint32_t)(j * 16), xs + (size_t)j * 4);
        }
        const uint32_t* wsrc = g_wp + s * 4608;
        #pragma unroll
        for (int j3 = 0; j3 < 3; j3++) {
            int j = tid + j3 * 512;              // 0..1151 (need 1152)
            if (j3 < 2 || j < 1152)
                cp16(wo + (uint32_t)(j * 16), wsrc + j * 4);
        }
        asm volatile("cp.async.commit_group;" ::: "memory");
    };

    const int cnt = (wid == 0) ? 3 : 2;          // tiles: t = wid + 16*i, 33 tiles

    float acc[3][4][4];
    #pragma unroll
    for (int mt = 0; mt < 3; mt++)
        #pragma unroll
        for (int nt = 0; nt < 4; nt++)
            #pragma unroll
            for (int q = 0; q < 4; q++)
                acc[mt][nt][q] = 0.0f;

    stage(0);

    for (int s = 0; s < 9; s++) {
        if (s < 8) {
            stage(s + 1);
            asm volatile("cp.async.wait_group 1;" ::: "memory");
        } else {
            asm volatile("cp.async.wait_group 0;" ::: "memory");
        }
        __syncthreads();

        const uint32_t xb = sb + ((s & 1) ? OFF_X1 : OFF_X0);
        const uint32_t wb = sb + ((s & 1) ? OFF_W1 : OFF_W0);

        #pragma unroll
        for (int tap = 0; tap < 9; tap++) {
            const int hk = tap / 3;
            const int tapoff = hk * 24 + (tap - 3 * hk);
            // B: row co = nt*8+g, 64B rows; quad c -> k = c,c+4 (kc0) / c+8,c+12 (kc1)
            uint32_t w0[4], w1[4], w2[4], w3[4];
            {
                const uint32_t wrow = wb + (uint32_t)(((tap * 32 + g) * 16 + c * 4) * 4);
                lds4(w0[0], w1[0], w2[0], w3[0], wrow);
                lds4(w0[1], w1[1], w2[1], w3[1], wrow + 8 * 64);
                lds4(w0[2], w1[2], w2[2], w3[2], wrow + 16 * 64);
                lds4(w0[3], w1[3], w2[3], w3[3], wrow + 24 * 64);
            }
            const uint32_t xrow = xb + (uint32_t)(((g + tapoff) * 16 + c * 4) * 4);
            #pragma unroll
            for (int mt = 0; mt < 3; mt++) {
                if (mt >= cnt) break;
                const int m0 = (wid + 16 * mt) * 16;
                uint32_t l0, l1, l2, l3, h0, h1, h2, h3;
                lds4(l0, l1, l2, l3, xrow + m0 * 64);
                lds4(h0, h1, h2, h3, xrow + (m0 + 8) * 64);
                #pragma unroll
                for (int nt = 0; nt < 4; nt++)
                    MMA_TF32(acc[mt][nt], l0, h0, l1, h1, w0[nt], w1[nt]);
                #pragma unroll
                for (int nt = 0; nt < 4; nt++)
                    MMA_TF32(acc[mt][nt], l2, h2, l3, h3, w2[nt], w3[nt]);
            }
        }
        __syncthreads();
    }

    // ---- epilogue ----
    const float* bs = (const float*)(smem + OFF_BS);
    const int spat = l_out * 10648 + d_out * 484;
    for (int mt = 0; mt < cnt; mt++) {
        const int mb = (wid + 16 * mt) * 16 + g;
        #pragma unroll
        for (int hm = 0; hm < 2; hm++) {
            int m = mb + 8 * hm;
            int h = m / 24;
            int w = m - 24 * h;
            if (h < 22 && w < 22) {
                size_t pos = (size_t)spat + h * 22 + w;
                #pragma unroll
                for (int nt = 0; nt < 4; nt++) {
                    #pragma unroll
                    for (int hc = 0; hc < 2; hc++) {
                        int co = nt * 8 + 2 * c + hc;
                        out[(size_t)(n * 32 + co) * OUT_CO_STRIDE + pos] =
                            acc[mt][nt][hm * 2 + hc] + bs[co];
                    }
                }
            }
        }
    }
}

extern "C" void kernel_launch(void* const* d_in, const int* in_sizes, int n_in,
                              void* d_out, int out_size)
{
    const float* x = (const float*)d_in[0];
    const float* W = (const float*)d_in[1];
    const float* b = (const float*)d_in[2];
    float* out = (float*)d_out;

    dim3 pgrid(24, 32, 8);
    prep_x_kernel<<<pgrid, 256>>>(x);
    prep_w_kernel<<<162, 256>>>(W);

    cudaFuncSetAttribute(conv4d_mma_kernel,
                         cudaFuncAttributeMaxDynamicSharedMemorySize, SMEM_TOTAL);
    dim3 grid(22, 30, 8);   // (d_out, l_out, n)
    conv4d_mma_kernel<<<grid, 512, SMEM_TOTAL>>>(b, out);
}

// round 11
// speedup vs baseline: 1.0856x; 1.0856x over previous
#include <cuda_runtime.h>
#include <cstdint>

// Conv4D via mma.sync tf32 (portable sm_80+ PTX).
// x(8,16,32,24,24,24) NCLDHW * W(32,16,3,3,3,3) OILDHW -> out(8,32,30,22,22,22), +3*b.
//
// R11 = R7 geometry (384 thr, 12 warps, k-quad lds4 layout, double-buffered
// cp.async staging) + 2-stage REGISTER pipeline across taps: fragments for
// tap t+1 are loaded while tap t's MMAs issue, hiding LDS latency/crossbar
// under the tensor pipe.

#define XBUF 37120                 // 580 rows * 64B
#define OFF_X0 0
#define OFF_X1 37120
#define OFF_W0 74240               // 288 rows * 64B = 18432
#define OFF_W1 92672
#define OFF_BS 111104
#define SMEM_TOTAL 111232

#define L_STRIDE 13824             // 24*24*24
#define OUT_CO_STRIDE 319440       // 30*22*22*22

__device__ uint32_t g_xp[56623104];    // [n][l][d][m=576][16 ci quad-interleaved]
__device__ uint32_t g_wp[41472];       // [s][tap][co][16 ci quad-interleaved]

static __device__ __forceinline__ uint32_t s2u(const void* p) {
    uint32_t a;
    asm("{ .reg .u64 t; cvta.to.shared.u64 t, %1; cvt.u32.u64 %0, t; }" : "=r"(a) : "l"(p));
    return a;
}
static __device__ __forceinline__ uint32_t tf32rn(float f) {
    uint32_t o;
    asm("cvt.rna.tf32.f32 %0, %1;" : "=r"(o) : "f"(f));
    return o;
}
static __device__ __forceinline__ void cp16(uint32_t dst, const void* src) {
    asm volatile("cp.async.cg.shared.global [%0], [%1], 16;" :: "r"(dst), "l"(src) : "memory");
}
static __device__ __forceinline__ void lds4(uint32_t& r0, uint32_t& r1, uint32_t& r2, uint32_t& r3, uint32_t a) {
    asm volatile("ld.shared.v4.u32 {%0,%1,%2,%3}, [%4];" : "=r"(r0), "=r"(r1), "=r"(r2), "=r"(r3) : "r"(a));
}

#define MMA_TF32(d, a0, a1, a2, a3, b0, b1) \
    asm volatile("mma.sync.aligned.m16n8k8.row.col.f32.tf32.tf32.f32 " \
        "{%0,%1,%2,%3}, {%4,%5,%6,%7}, {%8,%9}, {%0,%1,%2,%3};" \
        : "+f"((d)[0]), "+f"((d)[1]), "+f"((d)[2]), "+f"((d)[3]) \
        : "r"(a0), "r"(a1), "r"(a2), "r"(a3), "r"(b0), "r"(b1))

// ---- prepass: x -> tf32 bits; within-row order pos = (ci%4)*4 + ci/4 ----
__global__ __launch_bounds__(256)
void prep_x_kernel(const float* __restrict__ x) {
    const int d = blockIdx.x, l = blockIdx.y, n = blockIdx.z;
    const int tid = threadIdx.x;
    const size_t src0 = ((size_t)(n * 16) * 32 + l) * L_STRIDE + d * 576;
    uint32_t* dst0 = g_xp + (((size_t)(n * 32 + l) * 24 + d) * 576) * 16;
    for (int m = tid; m < 576; m += 256) {
        uint32_t v[16];
        #pragma unroll
        for (int ci = 0; ci < 16; ci++)
            v[(ci & 3) * 4 + (ci >> 2)] = tf32rn(x[src0 + (size_t)ci * (32 * L_STRIDE) + m]);
        uint32_t* dr = dst0 + m * 16;
        #pragma unroll
        for (int q = 0; q < 4; q++)
            *(uint4*)(dr + q * 4) = make_uint4(v[q*4], v[q*4+1], v[q*4+2], v[q*4+3]);
    }
}

// ---- prepass: W -> tf32 bits, [s][tap][co][pos], ci = (pos>>2) + (pos&3)*4 ----
__global__ __launch_bounds__(256)
void prep_w_kernel(const float* __restrict__ W) {
    int e = blockIdx.x * 256 + threadIdx.x;     // 0..41471
    int pos = e & 15;
    int co  = (e >> 4) & 31;
    int t9  = e >> 9;                            // s*9+tap
    int s   = t9 / 9, tap = t9 - 9 * s;
    int lk = s / 3,  dk = s - 3 * lk;
    int hk = tap / 3, wk = tap - 3 * hk;
    int ci = (pos >> 2) + (pos & 3) * 4;
    g_wp[e] = tf32rn(W[(size_t)(co * 16 + ci) * 81 + lk * 27 + dk * 9 + hk * 3 + wk]);
}

extern __shared__ char smem[];

__global__ __launch_bounds__(384)
void conv4d_mma_kernel(const float* __restrict__ b, float* __restrict__ out)
{
    const int d_out = blockIdx.x;   // 0..21
    const int l_out = blockIdx.y;   // 0..29
    const int n     = blockIdx.z;   // 0..7
    const int tid   = threadIdx.x;
    const int wid   = tid >> 5;     // 0..11
    const int lid   = tid & 31;
    const int c     = lid & 3;
    const int g     = lid >> 2;
    const uint32_t sb = s2u(smem);

    if (tid < 32) ((float*)(smem + OFF_BS))[tid] = 3.0f * b[tid];

    auto stage = [&](int s) {
        const int lk = s / 3, dk = s - 3 * lk;
        const uint32_t xo = sb + ((s & 1) ? OFF_X1 : OFF_X0);
        const uint32_t wo = sb + ((s & 1) ? OFF_W1 : OFF_W0);
        const uint32_t* xs = g_xp + (((size_t)(n * 32 + (l_out + lk)) * 24 + (d_out + dk)) * 576) * 16;
        #pragma unroll
        for (int j6 = 0; j6 < 6; j6++) {
            int j = tid + j6 * 384;              // 0..2303
            cp16(xo + (uint32_t)(j * 16), xs + (size_t)j * 4);
        }
        const uint32_t* wsrc = g_wp + s * 4608;
        #pragma unroll
        for (int j3 = 0; j3 < 3; j3++) {
            int j = tid + j3 * 384;              // 0..1151
            cp16(wo + (uint32_t)(j * 16), wsrc + j * 4);
        }
        asm volatile("cp.async.commit_group;" ::: "memory");
    };

    const int cnt = (wid < 9) ? 3 : 2;           // tiles: t = wid + 12*i, 33 tiles

    float acc[3][4][4];
    #pragma unroll
    for (int mt = 0; mt < 3; mt++)
        #pragma unroll
        for (int nt = 0; nt < 4; nt++)
            #pragma unroll
            for (int q = 0; q < 4; q++)
                acc[mt][nt][q] = 0.0f;

    stage(0);

    uint32_t wreg[2][4][4];   // [buf][q][nt]
    uint32_t areg[2][3][8];   // [buf][mt][l0..l3,h0..h3]

    for (int s = 0; s < 9; s++) {
        if (s < 8) {
            stage(s + 1);
            asm volatile("cp.async.wait_group 1;" ::: "memory");
        } else {
            asm volatile("cp.async.wait_group 0;" ::: "memory");
        }
        __syncthreads();

        const uint32_t xb = sb + ((s & 1) ? OFF_X1 : OFF_X0);
        const uint32_t wb = sb + ((s & 1) ? OFF_W1 : OFF_W0);

        auto loadB = [&](int tap, uint32_t w[4][4]) {
            const uint32_t wrow = wb + (uint32_t)(((tap * 32 + g) * 16 + c * 4) * 4);
            #pragma unroll
            for (int nt = 0; nt < 4; nt++)
                lds4(w[0][nt], w[1][nt], w[2][nt], w[3][nt], wrow + nt * (8 * 64));
        };
        auto loadA = [&](int tap, uint32_t a[3][8]) {
            const int hk = tap / 3;
            const int tapoff = hk * 24 + (tap - 3 * hk);
            const uint32_t xrow = xb + (uint32_t)(((g + tapoff) * 16 + c * 4) * 4);
            #pragma unroll
            for (int mt = 0; mt < 3; mt++) {
                if (mt >= cnt) break;
                const int m0 = (wid + 12 * mt) * 16;
                lds4(a[mt][0], a[mt][1], a[mt][2], a[mt][3], xrow + m0 * 64);
                lds4(a[mt][4], a[mt][5], a[mt][6], a[mt][7], xrow + (m0 + 8) * 64);
            }
        };

        loadB(0, wreg[0]);
        loadA(0, areg[0]);

        #pragma unroll
        for (int tap = 0; tap < 9; tap++) {
            const int cb = tap & 1, nb = cb ^ 1;
            if (tap < 8) {
                loadB(tap + 1, wreg[nb]);
                loadA(tap + 1, areg[nb]);
            }
            #pragma unroll
            for (int mt = 0; mt < 3; mt++) {
                if (mt >= cnt) break;
                #pragma unroll
                for (int nt = 0; nt < 4; nt++)
                    MMA_TF32(acc[mt][nt],
                             areg[cb][mt][0], areg[cb][mt][4],
                             areg[cb][mt][1], areg[cb][mt][5],
                             wreg[cb][0][nt], wreg[cb][1][nt]);
                #pragma unroll
                for (int nt = 0; nt < 4; nt++)
                    MMA_TF32(acc[mt][nt],
                             areg[cb][mt][2], areg[cb][mt][6],
                             areg[cb][mt][3], areg[cb][mt][7],
                             wreg[cb][2][nt], wreg[cb][3][nt]);
            }
        }
        __syncthreads();
    }

    // ---- epilogue ----
    const float* bs = (const float*)(smem + OFF_BS);
    const int spat = l_out * 10648 + d_out * 484;
    for (int mt = 0; mt < cnt; mt++) {
        const int mb = (wid + 12 * mt) * 16 + g;
        #pragma unroll
        for (int hm = 0; hm < 2; hm++) {
            int m = mb + 8 * hm;
            int h = m / 24;
            int w = m - 24 * h;
            if (h < 22 && w < 22) {
                size_t pos = (size_t)spat + h * 22 + w;
                #pragma unroll
                for (int nt = 0; nt < 4; nt++) {
                    #pragma unroll
                    for (int hc = 0; hc < 2; hc++) {
                        int co = nt * 8 + 2 * c + hc;
                        out[(size_t)(n * 32 + co) * OUT_CO_STRIDE + pos] =
                            acc[mt][nt][hm * 2 + hc] + bs[co];
                    }
                }
            }
        }
    }
}

extern "C" void kernel_launch(void* const* d_in, const int* in_sizes, int n_in,
                              void* d_out, int out_size)
{
    const float* x = (const float*)d_in[0];
    const float* W = (const float*)d_in[1];
    const float* b = (const float*)d_in[2];
    float* out = (float*)d_out;

    dim3 pgrid(24, 32, 8);
    prep_x_kernel<<<pgrid, 256>>>(x);
    prep_w_kernel<<<162, 256>>>(W);

    cudaFuncSetAttribute(conv4d_mma_kernel,
                         cudaFuncAttributeMaxDynamicSharedMemorySize, SMEM_TOTAL);
    dim3 grid(22, 30, 8);   // (d_out, l_out, n)
    conv4d_mma_kernel<<<grid, 384, SMEM_TOTAL>>>(b, out);
}